// round 9
// baseline (speedup 1.0000x reference)
#include <cuda_runtime.h>

#define T_  256
#define B_  64
#define H_  1024
#define G3  3072
#define I_  2048
#define TB  16384   // T_*B_

// smem words: Ws[48*1024] | Hb[2][4096] | mbar full[2], empty[2], red[1]
#define WS_WORDS  (48 * 1024)
#define HB_WORDS  4096                       // one 64x64 tf32 chunk (16KB)
#define MBAR_OFF  (WS_WORDS + 2 * HB_WORDS)  // word offset of barriers
#define SMEM_STEP ((MBAR_OFF + 10) * 4)      // 229,416 B

// ---------------- scratch (static device allocations: allowed) --------------
__device__ float g_gi[2][(size_t)TB * G3];     // input projections per direction
__device__ float g_buf[2][(size_t)TB * I_];    // inter-layer activations
// h exchange: tf32 bits, blocked [chunk=k/64][b][k%64], XOR swizzle baked in
__device__ __align__(1024) unsigned g_htf[2][2][B_ * H_];
__device__ unsigned g_cflag[2][16];            // per-(dir,chunk) producer counts
__device__ unsigned g_done[2];                 // per-dir lagged step counter

// ---------------- helpers ---------------------------------------------------
__device__ __forceinline__ unsigned f2tf(float f) {
    unsigned u;
    asm("cvt.rna.tf32.f32 %0, %1;" : "=r"(u) : "f"(f));
    return u;
}

__device__ __forceinline__ void mma8(float* c, const unsigned* a, const unsigned* b) {
    asm volatile(
        "mma.sync.aligned.m16n8k8.row.col.f32.tf32.tf32.f32 "
        "{%0,%1,%2,%3}, {%4,%5,%6,%7}, {%8,%9}, {%0,%1,%2,%3};"
        : "+f"(c[0]), "+f"(c[1]), "+f"(c[2]), "+f"(c[3])
        : "r"(a[0]), "r"(a[1]), "r"(a[2]), "r"(a[3]),
          "r"(b[0]), "r"(b[1]));
}

__device__ __forceinline__ void mbar_wait(unsigned mb, unsigned par) {
    asm volatile(
        "{\n\t.reg .pred P;\n"
        "W_%=:\n\t"
        "mbarrier.try_wait.parity.shared::cta.b64 P, [%0], %1;\n\t"
        "@!P bra W_%=;\n\t}"
        :: "r"(mb), "r"(par) : "memory");
}

__device__ __forceinline__ unsigned ldacq(const unsigned* p) {
    unsigned v;
    asm volatile("ld.acquire.gpu.global.u32 %0, [%1];"
                 : "=r"(v) : "l"(p) : "memory");
    return v;
}

// blocked+swizzled index of h[b][k] in g_htf
__device__ __forceinline__ int hidx(int b, int k) {
    return (k >> 6) * 4096 + b * 64 + ((k & 63) ^ ((b & 7) << 2));
}

// ---------------- input projection GEMM v3 (RF double-buffer) ---------------
// CTA tile 128x128, 8 warps (2m x 4n), warp tile 64x32, XOR-swizzled smem.
// Next k-tile prefetched into registers while current computes.
__global__ __launch_bounds__(256, 2) void gemm_gi_kernel(
    const float* __restrict__ x, const float* __restrict__ w_ih,
    const float* __restrict__ b_ih, int l)
{
    const int d = blockIdx.z;
    const float* A    = (l == 0) ? x : g_buf[l - 1];
    const float* W    = w_ih + (size_t)(l * 2 + d) * G3 * I_;
    const float* bias = b_ih + (l * 2 + d) * G3;
    float* C = g_gi[d];

    __shared__ unsigned As[128 * 32];
    __shared__ unsigned Bs[128 * 32];

    const int tid  = threadIdx.x;
    const int lane = tid & 31, warp = tid >> 5;
    const int wm = (warp & 1) * 64, wn = (warp >> 1) * 32;
    const int m0 = blockIdx.y * 128, n0 = blockIdx.x * 128;
    const int g8 = lane >> 2, tg = lane & 3;
    const unsigned swz = (unsigned)(g8 << 2);

    float acc[4][4][4];
    #pragma unroll
    for (int a = 0; a < 4; a++)
        #pragma unroll
        for (int b = 0; b < 4; b++)
            #pragma unroll
            for (int i = 0; i < 4; i++) acc[a][b][i] = 0.f;

    // per-thread granule mapping (4 granules per tile per thread)
    int rowi[4], cgi[4];
    #pragma unroll
    for (int i = 0; i < 4; i++) {
        int idx = tid + 256 * i;
        rowi[i] = idx >> 3; cgi[i] = (idx & 7) * 4;
    }

    float4 ra[4], rbv[4];
    #pragma unroll
    for (int i = 0; i < 4; i++) {          // preload kt=0 into RF
        ra[i]  = __ldg(reinterpret_cast<const float4*>(
                     &A[(size_t)(m0 + rowi[i]) * I_ + cgi[i]]));
        rbv[i] = __ldg(reinterpret_cast<const float4*>(
                     &W[(size_t)(n0 + rowi[i]) * I_ + cgi[i]]));
    }

    for (int kt = 0; kt < I_; kt += 32) {
        #pragma unroll
        for (int i = 0; i < 4; i++) {      // cvt + store current tile
            unsigned* p = &As[rowi[i] * 32 + (cgi[i] ^ ((rowi[i] & 7) << 2))];
            p[0] = f2tf(ra[i].x); p[1] = f2tf(ra[i].y);
            p[2] = f2tf(ra[i].z); p[3] = f2tf(ra[i].w);
            unsigned* q = &Bs[rowi[i] * 32 + (cgi[i] ^ ((rowi[i] & 7) << 2))];
            q[0] = f2tf(rbv[i].x); q[1] = f2tf(rbv[i].y);
            q[2] = f2tf(rbv[i].z); q[3] = f2tf(rbv[i].w);
        }
        __syncthreads();
        if (kt + 32 < I_) {                // prefetch next tile (hidden by mma)
            #pragma unroll
            for (int i = 0; i < 4; i++) {
                ra[i]  = __ldg(reinterpret_cast<const float4*>(
                             &A[(size_t)(m0 + rowi[i]) * I_ + kt + 32 + cgi[i]]));
                rbv[i] = __ldg(reinterpret_cast<const float4*>(
                             &W[(size_t)(n0 + rowi[i]) * I_ + kt + 32 + cgi[i]]));
            }
        }
        #pragma unroll
        for (int kk = 0; kk < 32; kk += 8) {
            unsigned af[4][4], bf[4][2];
            #pragma unroll
            for (int mt = 0; mt < 4; mt++) {
                int r = wm + mt * 16 + g8;
                af[mt][0] = As[r * 32 + ((unsigned)(kk + tg) ^ swz)];
                af[mt][1] = As[(r + 8) * 32 + ((unsigned)(kk + tg) ^ swz)];
                af[mt][2] = As[r * 32 + ((unsigned)(kk + tg + 4) ^ swz)];
                af[mt][3] = As[(r + 8) * 32 + ((unsigned)(kk + tg + 4) ^ swz)];
            }
            #pragma unroll
            for (int nt = 0; nt < 4; nt++) {
                int r = wn + nt * 8 + g8;
                bf[nt][0] = Bs[r * 32 + ((unsigned)(kk + tg) ^ swz)];
                bf[nt][1] = Bs[r * 32 + ((unsigned)(kk + tg + 4) ^ swz)];
            }
            #pragma unroll
            for (int mt = 0; mt < 4; mt++)
                #pragma unroll
                for (int nt = 0; nt < 4; nt++)
                    mma8(acc[mt][nt], af[mt], bf[nt]);
        }
        __syncthreads();
    }

    #pragma unroll
    for (int mt = 0; mt < 4; mt++)
        #pragma unroll
        for (int nt = 0; nt < 4; nt++)
            #pragma unroll
            for (int i = 0; i < 4; i++) {
                int row = m0 + wm + mt * 16 + g8 + 8 * (i >> 1);
                int col = n0 + wn + nt * 8 + 2 * tg + (i & 1);
                C[(size_t)row * G3 + col] = acc[mt][nt][i] + __ldg(&bias[col]);
            }
}

// ---------------- h0 init & flag reset --------------------------------------
__global__ void init_h_kernel(const float* __restrict__ h0, int l)
{
    int i = blockIdx.x * blockDim.x + threadIdx.x;
    if (i < 2 * B_ * H_) {
        int dir = i >> 16, rem = i & 65535;
        int b = rem >> 10, k = rem & 1023;
        float v = h0[(size_t)(2 * l + dir) * B_ * H_ + rem];
        g_htf[0][dir][hidx(b, k)] = f2tf(v);
    }
    if (i < 32) g_cflag[i >> 4][i & 15] = 4u;   // h0 counts as step-0 data
    if (i < 2)  g_done[i] = 0u;
}

// ---------------- persistent recurrent kernel -------------------------------
// 128 CTAs (1/SM, 229KB smem), 544 threads: 16 compute warps + 1 control.
// Warp map: ks=warp>>2 (4-way K split, kk in [ks*16,ks*16+16) of each chunk),
// sub=warp&3 -> rb=(sub&1)*32 (M=32), jh=sub>>1 (N=24: 3 gates x 8 j).
// Smem volume/step 896KB (was 1280KB). Reduction in Hb guarded by mb_red.
extern __shared__ unsigned smem_dyn[];

__global__ __launch_bounds__(544, 1) void gru_persistent_kernel(
    const float* __restrict__ w_hh, const float* __restrict__ b_hh,
    const float* __restrict__ h0, float* __restrict__ d_out, int l)
{
    const int cta = blockIdx.x;
    const int dir = cta >> 6;
    const int j0  = (cta & 63) * 16;
    const int cj  = (cta & 63) >> 2;         // chunk this CTA produces
    const float* W  = w_hh + (size_t)(l * 2 + dir) * G3 * H_;
    const float* bh = b_hh + (l * 2 + dir) * G3;
    float* y = (l == 2) ? d_out : g_buf[l];

    unsigned* Ws = smem_dyn;                 // 48*1024 words, swizzled
    unsigned* Hb = smem_dyn + WS_WORDS;      // 2 x 4096-word TMA buffers
    const unsigned hb_u32 = (unsigned)__cvta_generic_to_shared(Hb);
    const unsigned mb_full  = (unsigned)__cvta_generic_to_shared(smem_dyn + MBAR_OFF);
    const unsigned mb_empty = mb_full + 16;
    const unsigned mb_red   = mb_full + 32;

    const int tid  = threadIdx.x;
    const int lane = tid & 31, warp = tid >> 5;
    const int ks  = (warp < 16) ? (warp >> 2) : 0;   // K quarter (0..3)
    const int sub = warp & 3;
    const int rb  = (sub & 1) * 32;          // B rows base (M=32 per warp)
    const int jh  = sub >> 1;                // j half (0,1)
    const int g8 = lane >> 2, tg = lane & 3;
    const unsigned swz = (unsigned)(g8 << 2);

    // ---- load W slice once (swizzled: word = row*1024 + (col ^ ((row&7)<<2)))
    if (tid < 512) {
        #pragma unroll 4
        for (int i = 0; i < 24; i++) {
            int idx = tid + 512 * i;
            int row = idx >> 8;              // 0..47
            int c4  = (idx & 255) * 4;
            int g = row >> 4, jj = row & 15;
            float4 v = *reinterpret_cast<const float4*>(
                &W[(size_t)(g * H_ + j0 + jj) * H_ + c4]);
            unsigned* w = &Ws[row * 1024 + (c4 ^ ((row & 7) << 2))];
            w[0] = f2tf(v.x); w[1] = f2tf(v.y); w[2] = f2tf(v.z); w[3] = f2tf(v.w);
        }
    }

    // ---- bias & initial h_prev registers (owner warps ks==0) ----
    const int jA = j0 + jh * 8 + 2 * tg;
    float bhv[3][2], hpv[8];
    if (warp < 16 && ks == 0) {
        #pragma unroll
        for (int g = 0; g < 3; g++) {
            bhv[g][0] = __ldg(&bh[g * H_ + jA]);
            bhv[g][1] = __ldg(&bh[g * H_ + jA + 1]);
        }
        #pragma unroll
        for (int mt = 0; mt < 2; mt++)
            #pragma unroll
            for (int i = 0; i < 4; i++) {
                int b = rb + mt * 16 + g8 + 8 * (i >> 1);
                hpv[mt * 4 + i] = __ldg(&h0[(size_t)(2 * l + dir) * B_ * H_
                                            + (size_t)b * H_ + jA + (i & 1)]);
            }
    }

    // ---- mbarrier init: full cnt 1, empty cnt 16, red cnt 4 ----
    if (tid == 0) {
        #pragma unroll
        for (int m = 0; m < 2; m++) {
            asm volatile("mbarrier.init.shared.b64 [%0], 1;"
                         :: "r"(mb_full + m * 8) : "memory");
            asm volatile("mbarrier.init.shared.b64 [%0], 16;"
                         :: "r"(mb_empty + m * 8) : "memory");
        }
        asm volatile("mbarrier.init.shared.b64 [%0], 4;"
                     :: "r"(mb_red) : "memory");
        asm volatile("fence.proxy.async.shared::cta;" ::: "memory");
    }
    __syncthreads();

    unsigned fuse[2] = {0, 0};               // compute: full-phase counters
    unsigned euse[2] = {0, 0};               // control: slot use counters
    unsigned red_phase = 0;                  // control: reduction-free phase

    for (int s = 0; s < T_; s++) {
        const int t = dir ? (T_ - 1 - s) : s;
        const unsigned* src = g_htf[s & 1][dir];
        unsigned* dstg = g_htf[(s + 1) & 1][dir];

        if (warp == 16) {
            // -------- control warp: issue all 16 chunk TMAs ---------------
            if (lane == 0) {
                // wait until prior step's reduction finished reading Hb
                if (s > 0) { mbar_wait(mb_red, red_phase); red_phase ^= 1; }
                const unsigned tgt = 4u * (unsigned)(s + 1);
                for (int c = 0; c < 16; c++) {
                    int slot = c & 1;
                    if (euse[slot] > 0)
                        mbar_wait(mb_empty + slot * 8, (euse[slot] - 1) & 1);
                    euse[slot]++;
                    while (ldacq(&g_cflag[dir][c]) < tgt) __nanosleep(20);
                    unsigned mb = mb_full + slot * 8;
                    asm volatile("mbarrier.arrive.expect_tx.shared.b64 _, [%0], %1;"
                                 :: "r"(mb), "r"(16384u) : "memory");
                    asm volatile(
                        "cp.async.bulk.shared::cta.global.mbarrier::complete_tx::bytes "
                        "[%0], [%1], %2, [%3];"
                        :: "r"(hb_u32 + slot * (HB_WORDS * 4)),
                           "l"(src + c * HB_WORDS), "r"(16384u), "r"(mb)
                        : "memory");
                }
            }
        }

        float accf[24];                      // acc(mt,g,i) = accf[(mt*3+g)*4+i]
        #pragma unroll
        for (int q = 0; q < 24; q++) accf[q] = 0.f;

        float giv[3][8];
        if (warp < 16 && ks == 0) {          // gi prefetch overlaps GEMM
            #pragma unroll
            for (int mt = 0; mt < 2; mt++)
                #pragma unroll
                for (int p = 0; p < 2; p++) {
                    int b = rb + mt * 16 + g8 + 8 * p;
                    const float* gi = g_gi[dir] + (size_t)(t * B_ + b) * G3 + jA;
                    #pragma unroll
                    for (int g = 0; g < 3; g++) {
                        float2 v = __ldg(reinterpret_cast<const float2*>(gi + g * H_));
                        giv[g][mt * 4 + 2 * p]     = v.x;
                        giv[g][mt * 4 + 2 * p + 1] = v.y;
                    }
                }
        }

        if (warp < 16) {
            // -------- compute warps: consume 16 chunks --------------------
            for (int c = 0; c < 16; c++) {
                int slot = c & 1;
                mbar_wait(mb_full + slot * 8, fuse[slot] & 1);
                fuse[slot]++;

                const unsigned* hb = Hb + slot * HB_WORDS;
                #pragma unroll
                for (int kk2 = 0; kk2 < 16; kk2 += 8) {
                    const int kc = ks * 16 + kk2;          // col in chunk
                    unsigned af[2][4];
                    #pragma unroll
                    for (int mt = 0; mt < 2; mt++) {
                        int r0 = rb + mt * 16 + g8;
                        af[mt][0] = hb[r0 * 64       + ((unsigned)(kc + tg)     ^ swz)];
                        af[mt][1] = hb[(r0 + 8) * 64 + ((unsigned)(kc + tg)     ^ swz)];
                        af[mt][2] = hb[r0 * 64       + ((unsigned)(kc + tg + 4) ^ swz)];
                        af[mt][3] = hb[(r0 + 8) * 64 + ((unsigned)(kc + tg + 4) ^ swz)];
                    }
                    const int kw = c * 64 + kc;            // global k in W
                    #pragma unroll
                    for (int g = 0; g < 3; g++) {
                        const int wr = g * 16 + jh * 8 + g8;
                        unsigned bf[2];
                        bf[0] = Ws[wr * 1024 + ((unsigned)(kw + tg) ^ swz)];
                        bf[1] = Ws[wr * 1024 + ((unsigned)(kw + tg + 4) ^ swz)];
                        mma8(&accf[(0 * 3 + g) * 4], af[0], bf);
                        mma8(&accf[(1 * 3 + g) * 4], af[1], bf);
                    }
                }
                if (lane == 0)
                    asm volatile("mbarrier.arrive.shared.b64 _, [%0];"
                                 :: "r"(mb_empty + slot * 8) : "memory");
            }
        }

        __syncthreads();                     // sync1: all chunks consumed

        // ---- 4-way K reduction, word-major [24][128], 2 regions in Hb ----
        float* red = reinterpret_cast<float*>(Hb);
        const int slot24 = sub * 32 + lane;
        if (warp < 16 && ks == 3) {
            #pragma unroll
            for (int q = 0; q < 24; q++) red[q * 128 + slot24] = accf[q];
        }
        __syncthreads();                     // sync2
        if (warp < 16 && ks == 2) {          // merge ks3, republish
            #pragma unroll
            for (int q = 0; q < 24; q++) {
                accf[q] += red[q * 128 + slot24];
                red[q * 128 + slot24] = accf[q];
            }
        }
        if (warp < 16 && ks == 1) {
            #pragma unroll
            for (int q = 0; q < 24; q++) red[3072 + q * 128 + slot24] = accf[q];
        }
        if (tid == 0 && s > 0) {             // lagged h-buffer write gate
            const unsigned tgt = 64u * (unsigned)s;
            while (ldacq(&g_done[dir]) < tgt) __nanosleep(20);
        }
        __syncthreads();                     // sync3

        if (warp < 16 && ks == 0) {
            #pragma unroll
            for (int q = 0; q < 24; q++)
                accf[q] += red[q * 128 + slot24] + red[3072 + q * 128 + slot24];
            if (lane == 0)                   // reduction reads done -> free Hb
                asm volatile("mbarrier.arrive.shared.b64 _, [%0];"
                             :: "r"(mb_red) : "memory");

            // ---- gate math (r,z,n), h update ----
            #pragma unroll
            for (int mt = 0; mt < 2; mt++)
                #pragma unroll
                for (int i = 0; i < 4; i++) {
                    float a0 = accf[(mt * 3 + 0) * 4 + i];
                    float a1 = accf[(mt * 3 + 1) * 4 + i];
                    float a2 = accf[(mt * 3 + 2) * 4 + i];
                    float r = 1.f / (1.f + expf(-(giv[0][mt * 4 + i] + a0 + bhv[0][i & 1])));
                    float z = 1.f / (1.f + expf(-(giv[1][mt * 4 + i] + a1 + bhv[1][i & 1])));
                    float n = tanhf(giv[2][mt * 4 + i] + r * (a2 + bhv[2][i & 1]));
                    hpv[mt * 4 + i] = (1.f - z) * n + z * hpv[mt * 4 + i];
                }
            #pragma unroll
            for (int mt = 0; mt < 2; mt++)
                #pragma unroll
                for (int p = 0; p < 2; p++) {
                    int b = rb + mt * 16 + g8 + 8 * p;
                    uint2 u = make_uint2(f2tf(hpv[mt * 4 + 2 * p]),
                                         f2tf(hpv[mt * 4 + 2 * p + 1]));
                    __stcg(reinterpret_cast<uint2*>(&dstg[hidx(b, jA)]), u);
                }
        }
        __syncthreads();                     // sync4: h stores done CTA-wide

        if (tid == 0) {
            __threadfence();                 // cumulative release of h stores
            atomicAdd(&g_cflag[dir][cj], 1u);
            atomicAdd(&g_done[dir], 1u);
        }
        if (warp < 16 && ks == 0) {          // y stores off the critical path
            #pragma unroll
            for (int mt = 0; mt < 2; mt++)
                #pragma unroll
                for (int p = 0; p < 2; p++) {
                    int b = rb + mt * 16 + g8 + 8 * p;
                    float2 v = make_float2(hpv[mt * 4 + 2 * p],
                                           hpv[mt * 4 + 2 * p + 1]);
                    *reinterpret_cast<float2*>(
                        &y[(size_t)(t * B_ + b) * 2048 + dir * H_ + jA]) = v;
                }
        }
    }
}

// ---------------- launch ------------------------------------------------------
extern "C" void kernel_launch(void* const* d_in, const int* in_sizes, int n_in,
                              void* d_out, int out_size)
{
    const float* x    = (const float*)d_in[0];
    const float* h0   = (const float*)d_in[1];
    const float* w_ih = (const float*)d_in[2];
    const float* w_hh = (const float*)d_in[3];
    const float* b_ih = (const float*)d_in[4];
    const float* b_hh = (const float*)d_in[5];
    float* out = (float*)d_out;

    cudaFuncSetAttribute(gru_persistent_kernel,
                         cudaFuncAttributeMaxDynamicSharedMemorySize,
                         SMEM_STEP);

    for (int l = 0; l < 3; l++) {
        dim3 gg(G3 / 128, TB / 128, 2);
        gemm_gi_kernel<<<gg, 256>>>(x, w_ih, b_ih, l);
        init_h_kernel<<<(2 * B_ * H_ + 255) / 256, 256>>>(h0, l);
        gru_persistent_kernel<<<128, 544, SMEM_STEP>>>(w_hh, b_hh, h0, out, l);
    }
}

// round 11
// speedup vs baseline: 1.4229x; 1.4229x over previous
#include <cuda_runtime.h>
#include <cuda_fp16.h>

#define T_  256
#define B_  64
#define H_  1024
#define G3  3072
#define I_  2048
#define TB  16384   // T_*B_

// smem words: Ws[48*512] | Hb[2][2048] | red[3072] | mbar[8]
#define WS_WORDS   (48 * 512)                // W: 96KB fp16
#define HB_SLOT_W  2048                      // one 64x64 fp16 chunk (8KB)
#define RED_OFF    (WS_WORDS + 2 * HB_SLOT_W)
#define RED_WORDS  3072
#define MBAR_W     (RED_OFF + RED_WORDS)
#define SMEM_STEP  ((MBAR_W + 8) * 4)        // ~127KB (still 1 CTA/SM)

// ---------------- scratch ----------------------------------------------------
__device__ float g_gi[2][(size_t)TB * G3];
__device__ float g_buf[2][(size_t)TB * I_];
// h: fp16 pairs; per (parity,dir): 16 chunks x 2048 words; chunk = 64 rows x
// 32 words; word(b,kw) = (kw>>5)*2048 + b*32 + ((kw&31) ^ ((b&7)<<2))
__device__ __align__(1024) unsigned g_htf[2][2][B_ * H_ / 2];
__device__ unsigned g_cflag[2][16];          // per-(dir,chunk) producer counts
__device__ unsigned g_done[2];               // per-dir completed-read counter

// ---------------- helpers ---------------------------------------------------
__device__ __forceinline__ unsigned f2h2(float lo, float hi) {
    unsigned u;                              // pack: lower=lo, upper=hi
    asm("cvt.rn.f16x2.f32 %0, %1, %2;" : "=r"(u) : "f"(hi), "f"(lo));
    return u;
}
__device__ __forceinline__ void mmah(float* c, const unsigned* a, const unsigned* b) {
    asm volatile(
        "mma.sync.aligned.m16n8k16.row.col.f32.f16.f16.f32 "
        "{%0,%1,%2,%3}, {%4,%5,%6,%7}, {%8,%9}, {%0,%1,%2,%3};"
        : "+f"(c[0]), "+f"(c[1]), "+f"(c[2]), "+f"(c[3])
        : "r"(a[0]), "r"(a[1]), "r"(a[2]), "r"(a[3]), "r"(b[0]), "r"(b[1]));
}
__device__ __forceinline__ void mbar_wait(unsigned mb, unsigned par) {
    asm volatile(
        "{\n\t.reg .pred P;\nW_%=:\n\t"
        "mbarrier.try_wait.parity.shared::cta.b64 P, [%0], %1;\n\t"
        "@!P bra W_%=;\n\t}" :: "r"(mb), "r"(par) : "memory");
}
__device__ __forceinline__ unsigned ldacq(const unsigned* p) {
    unsigned v;
    asm volatile("ld.acquire.gpu.global.u32 %0, [%1];" : "=r"(v) : "l"(p) : "memory");
    return v;
}
// word index of h pair (b, kw) in g_htf  (kw = k/2, 0..511)
__device__ __forceinline__ int widx(int b, int kw) {
    return (kw >> 5) * 2048 + b * 32 + ((kw & 31) ^ ((b & 7) << 2));
}

// ---------------- input projection GEMM (fp16 m16n8k16) ---------------------
// CTA tile 128x128, 8 warps (2m x 4n), warp tile 64x32. Smem word stride 20
// (conflict-free fragment loads: 20*g8 mod 32 covers {0,4,..,28}).
__global__ __launch_bounds__(256) void gemm_gi_kernel(
    const float* __restrict__ x, const float* __restrict__ w_ih,
    const float* __restrict__ b_ih, int l)
{
    const int d = blockIdx.z;
    const float* A    = (l == 0) ? x : g_buf[l - 1];
    const float* W    = w_ih + (size_t)(l * 2 + d) * G3 * I_;
    const float* bias = b_ih + (l * 2 + d) * G3;
    float* C = g_gi[d];

    __shared__ unsigned As[128 * 20];
    __shared__ unsigned Bs[128 * 20];

    const int tid  = threadIdx.x;
    const int lane = tid & 31, warp = tid >> 5;
    const int wm = (warp & 1) * 64, wn = (warp >> 1) * 32;
    const int m0 = blockIdx.y * 128, n0 = blockIdx.x * 128;
    const int g8 = lane >> 2, tg = lane & 3;

    float acc[4][4][4];
    #pragma unroll
    for (int a = 0; a < 4; a++)
        #pragma unroll
        for (int b = 0; b < 4; b++)
            #pragma unroll
            for (int i = 0; i < 4; i++) acc[a][b][i] = 0.f;

    for (int kt = 0; kt < I_; kt += 32) {
        #pragma unroll
        for (int i = 0; i < 4; i++) {            // A tile 128x32 f32 -> h2
            int idx = tid + 256 * i;
            int row = idx >> 3, c4 = (idx & 7) * 4, wc = (idx & 7) * 2;
            float4 v = *reinterpret_cast<const float4*>(
                &A[(size_t)(m0 + row) * I_ + kt + c4]);
            uint2 u = make_uint2(f2h2(v.x, v.y), f2h2(v.z, v.w));
            *reinterpret_cast<uint2*>(&As[row * 20 + wc]) = u;
        }
        #pragma unroll
        for (int i = 0; i < 4; i++) {            // B tile 128x32 (W rows)
            int idx = tid + 256 * i;
            int row = idx >> 3, c4 = (idx & 7) * 4, wc = (idx & 7) * 2;
            float4 v = *reinterpret_cast<const float4*>(
                &W[(size_t)(n0 + row) * I_ + kt + c4]);
            uint2 u = make_uint2(f2h2(v.x, v.y), f2h2(v.z, v.w));
            *reinterpret_cast<uint2*>(&Bs[row * 20 + wc]) = u;
        }
        __syncthreads();
        #pragma unroll
        for (int kk2 = 0; kk2 < 16; kk2 += 8) {  // two k16 mma steps
            unsigned af[4][4], bf[4][2];
            #pragma unroll
            for (int mt = 0; mt < 4; mt++) {
                int r = wm + mt * 16 + g8;
                af[mt][0] = As[r * 20 + kk2 + tg];
                af[mt][1] = As[(r + 8) * 20 + kk2 + tg];
                af[mt][2] = As[r * 20 + kk2 + tg + 4];
                af[mt][3] = As[(r + 8) * 20 + kk2 + tg + 4];
            }
            #pragma unroll
            for (int nt = 0; nt < 4; nt++) {
                int r = wn + nt * 8 + g8;
                bf[nt][0] = Bs[r * 20 + kk2 + tg];
                bf[nt][1] = Bs[r * 20 + kk2 + tg + 4];
            }
            #pragma unroll
            for (int mt = 0; mt < 4; mt++)
                #pragma unroll
                for (int nt = 0; nt < 4; nt++)
                    mmah(acc[mt][nt], af[mt], bf[nt]);
        }
        __syncthreads();
    }
    #pragma unroll
    for (int mt = 0; mt < 4; mt++)
        #pragma unroll
        for (int nt = 0; nt < 4; nt++)
            #pragma unroll
            for (int i = 0; i < 4; i++) {
                int row = m0 + wm + mt * 16 + g8 + 8 * (i >> 1);
                int col = n0 + wn + nt * 8 + 2 * tg + (i & 1);
                C[(size_t)row * G3 + col] = acc[mt][nt][i] + __ldg(&bias[col]);
            }
}

// ---------------- h0 init & flag reset --------------------------------------
__global__ void init_h_kernel(const float* __restrict__ h0, int l)
{
    int i = blockIdx.x * blockDim.x + threadIdx.x;
    if (i < 2 * B_ * H_ / 2) {
        int dir = i >> 15, w = i & 32767;
        int b = w >> 9, kw = w & 511;
        const float* p = &h0[(size_t)(2 * l + dir) * B_ * H_ + (size_t)b * H_ + 2 * kw];
        g_htf[0][dir][widx(b, kw)] = f2h2(p[0], p[1]);
    }
    if (i < 32) g_cflag[i >> 4][i & 15] = 4u;   // h0 counts as step-0 data
    if (i < 2)  g_done[i] = 0u;
}

// ---------------- persistent recurrent kernel (fp16) ------------------------
// 128 CTAs (1/SM), 544 threads: 16 compute warps (ks x jh x rb) + 1 control.
// W_hh slice 48x1024 fp16 (96KB, swizzled) resident all 256 steps. h chunks
// (8KB) streamed via TMA bulk; reduction in DEDICATED smem (no TMA race).
extern __shared__ unsigned smem_dyn[];

__global__ __launch_bounds__(544, 1) void gru_persistent_kernel(
    const float* __restrict__ w_hh, const float* __restrict__ b_hh,
    const float* __restrict__ h0, float* __restrict__ d_out, int l)
{
    const int cta = blockIdx.x;
    const int dir = cta >> 6;
    const int j0  = (cta & 63) * 16;
    const int cj  = (cta & 63) >> 2;         // chunk this CTA co-produces
    const float* Wg = w_hh + (size_t)(l * 2 + dir) * G3 * H_;
    const float* bh = b_hh + (l * 2 + dir) * G3;
    float* y = (l == 2) ? d_out : g_buf[l];

    unsigned* Ws = smem_dyn;                 // 48*512 words, swizzled
    unsigned* Hb = smem_dyn + WS_WORDS;      // 2 x 2048-word TMA buffers
    float* red = reinterpret_cast<float*>(smem_dyn + RED_OFF);
    const unsigned hb_u32 = (unsigned)__cvta_generic_to_shared(Hb);
    const unsigned mb_full  = (unsigned)__cvta_generic_to_shared(smem_dyn + MBAR_W);
    const unsigned mb_empty = mb_full + 16;

    const int tid  = threadIdx.x;
    const int lane = tid & 31, warp = tid >> 5;
    const int ks = (warp < 16) ? (warp >> 3) : 0;    // K half
    const int rb = (warp & 3) * 16;          // B rows of this warp
    const int jh = (warp >> 2) & 1;          // j half (0,1)
    const int gq = lane >> 2, tg = lane & 3;
    const unsigned swz = (unsigned)(gq << 2);
    const int kclo = ks * 16;                // word base within chunk's 32

    // ---- load W once: row=gate*16+jj, word(row,wc)=row*512+(wc^((row&7)<<2))
    if (tid < 512) {
        #pragma unroll 4
        for (int i = 0; i < 24; i++) {
            int idx = tid + 512 * i;         // 12288 float4 granules
            int row = idx >> 8, c4 = (idx & 255) * 4, wc = (idx & 255) * 2;
            int g = row >> 4, jj = row & 15;
            float4 v = *reinterpret_cast<const float4*>(
                &Wg[(size_t)(g * H_ + j0 + jj) * H_ + c4]);
            uint2 u = make_uint2(f2h2(v.x, v.y), f2h2(v.z, v.w));
            *reinterpret_cast<uint2*>(
                &Ws[row * 512 + (wc ^ ((row & 7) << 2))]) = u;
        }
    }

    // ---- bias & initial h_prev registers (ks==0 warps) ----
    const int jA = j0 + jh * 8 + 2 * tg;
    float bhv[3][2], hpv[4];
    if (warp < 16 && ks == 0) {
        #pragma unroll
        for (int g = 0; g < 3; g++) {
            bhv[g][0] = __ldg(&bh[g * H_ + jA]);
            bhv[g][1] = __ldg(&bh[g * H_ + jA + 1]);
        }
        #pragma unroll
        for (int i = 0; i < 4; i++) {
            int b = rb + gq + 8 * (i >> 1);
            hpv[i] = __ldg(&h0[(size_t)(2 * l + dir) * B_ * H_
                               + (size_t)b * H_ + jA + (i & 1)]);
        }
    }

    // ---- mbarriers: full cnt 1 (tx), empty cnt 16 ----
    if (tid == 0) {
        #pragma unroll
        for (int m = 0; m < 2; m++) {
            asm volatile("mbarrier.init.shared.b64 [%0], 1;"
                         :: "r"(mb_full + m * 8) : "memory");
            asm volatile("mbarrier.init.shared.b64 [%0], 16;"
                         :: "r"(mb_empty + m * 8) : "memory");
        }
        asm volatile("fence.proxy.async.shared::cta;" ::: "memory");
    }
    __syncthreads();

    unsigned fuse[2] = {0, 0}, euse[2] = {0, 0};

    for (int s = 0; s < T_; s++) {
        const int t = dir ? (T_ - 1 - s) : s;
        const unsigned* src = g_htf[s & 1][dir];
        unsigned* dstg = g_htf[(s + 1) & 1][dir];

        if (warp == 16 && lane == 0) {
            // -------- control: issue all 16 chunk TMAs --------------------
            const unsigned tgt = 4u * (unsigned)(s + 1);
            for (int c = 0; c < 16; c++) {
                int slot = c & 1;
                if (euse[slot] > 0)
                    mbar_wait(mb_empty + slot * 8, (euse[slot] - 1) & 1);
                euse[slot]++;
                while (ldacq(&g_cflag[dir][c]) < tgt) __nanosleep(20);
                unsigned fm = mb_full + slot * 8;
                asm volatile("mbarrier.arrive.expect_tx.shared.b64 _, [%0], %1;"
                             :: "r"(fm), "r"(8192u) : "memory");
                asm volatile(
                    "cp.async.bulk.shared::cta.global.mbarrier::complete_tx::bytes "
                    "[%0], [%1], %2, [%3];"
                    :: "r"(hb_u32 + slot * (HB_SLOT_W * 4)),
                       "l"(src + c * HB_SLOT_W), "r"(8192u), "r"(fm) : "memory");
            }
        }

        float acc[3][4];
        #pragma unroll
        for (int g = 0; g < 3; g++)
            #pragma unroll
            for (int i = 0; i < 4; i++) acc[g][i] = 0.f;

        float giv[3][4];
        if (warp < 16 && ks == 0) {          // gi prefetch overlaps GEMM
            #pragma unroll
            for (int i = 0; i < 4; i++) {
                int b = rb + gq + 8 * (i >> 1);
                int j = jA + (i & 1);
                const float* gi = g_gi[dir] + (size_t)(t * B_ + b) * G3;
                giv[0][i] = __ldg(&gi[j]);
                giv[1][i] = __ldg(&gi[H_ + j]);
                giv[2][i] = __ldg(&gi[2 * H_ + j]);
            }
        }

        if (warp < 16) {
            // -------- compute warps: consume 16 chunks --------------------
            for (int c = 0; c < 16; c++) {
                int slot = c & 1;
                mbar_wait(mb_full + slot * 8, fuse[slot] & 1);
                fuse[slot]++;

                const unsigned* hb = Hb + slot * HB_SLOT_W;
                #pragma unroll
                for (int kk2 = 0; kk2 < 16; kk2 += 8) {
                    const int kc = kclo + kk2;           // word col in chunk
                    unsigned af[4];
                    int r0 = rb + gq;
                    af[0] = hb[r0 * 32       + ((unsigned)(kc + tg)     ^ swz)];
                    af[1] = hb[(r0 + 8) * 32 + ((unsigned)(kc + tg)     ^ swz)];
                    af[2] = hb[r0 * 32       + ((unsigned)(kc + tg + 4) ^ swz)];
                    af[3] = hb[(r0 + 8) * 32 + ((unsigned)(kc + tg + 4) ^ swz)];
                    const int kw = c * 32 + kc;          // global word in W
                    #pragma unroll
                    for (int g = 0; g < 3; g++) {
                        const int wr = g * 16 + jh * 8 + gq;
                        unsigned bf[2];
                        bf[0] = Ws[wr * 512 + ((unsigned)(kw + tg) ^ swz)];
                        bf[1] = Ws[wr * 512 + ((unsigned)(kw + tg + 4) ^ swz)];
                        mmah(acc[g], af, bf);
                    }
                }
                if (lane == 0)
                    asm volatile("mbarrier.arrive.shared.b64 _, [%0];"
                                 :: "r"(mb_empty + slot * 8) : "memory");
            }
        }

        __syncthreads();                     // sync1: all chunks consumed

        // ---- K-split partials into DEDICATED red region (no TMA race) ----
        if (warp < 16 && ks == 1) {
            int base = ((warp & 7) * 32 + lane) * 12;
            #pragma unroll
            for (int g = 0; g < 3; g++)
                #pragma unroll
                for (int i = 0; i < 4; i++) red[base + g * 4 + i] = acc[g][i];
        }
        if (tid == 0 && s > 0) {             // lagged h-buffer write gate
            const unsigned tgt = 64u * (unsigned)s;
            while (ldacq(&g_done[dir]) < tgt) __nanosleep(20);
        }
        __syncthreads();                     // sync2

        if (warp < 16 && ks == 0) {
            int base = (warp * 32 + lane) * 12;
            #pragma unroll
            for (int g = 0; g < 3; g++)
                #pragma unroll
                for (int i = 0; i < 4; i++) acc[g][i] += red[base + g * 4 + i];

            #pragma unroll
            for (int i = 0; i < 4; i++) {
                float r = 1.f / (1.f + expf(-(giv[0][i] + acc[0][i] + bhv[0][i & 1])));
                float z = 1.f / (1.f + expf(-(giv[1][i] + acc[1][i] + bhv[1][i & 1])));
                float n = tanhf(giv[2][i] + r * (acc[2][i] + bhv[2][i & 1]));
                hpv[i] = (1.f - z) * n + z * hpv[i];
            }
            // h store: one half2 word per b (pairs i=0,1 and i=2,3)
            const int kw = jA >> 1;
            #pragma unroll
            for (int p = 0; p < 2; p++) {
                int b = rb + gq + 8 * p;
                __stcg(&dstg[widx(b, kw)], f2h2(hpv[2 * p], hpv[2 * p + 1]));
            }
        }
        __syncthreads();                     // sync3: h stores done CTA-wide

        if (tid == 0) {
            __threadfence();                 // cumulative release of h stores
            atomicAdd(&g_cflag[dir][cj], 1u);
            atomicAdd(&g_done[dir], 1u);
        }
        if (warp < 16 && ks == 0) {          // y stores off the critical path
            #pragma unroll
            for (int p = 0; p < 2; p++) {
                int b = rb + gq + 8 * p;
                float2 v = make_float2(hpv[2 * p], hpv[2 * p + 1]);
                *reinterpret_cast<float2*>(
                    &y[(size_t)(t * B_ + b) * 2048 + dir * H_ + jA]) = v;
            }
        }
    }
}

// ---------------- launch ------------------------------------------------------
extern "C" void kernel_launch(void* const* d_in, const int* in_sizes, int n_in,
                              void* d_out, int out_size)
{
    const float* x    = (const float*)d_in[0];
    const float* h0   = (const float*)d_in[1];
    const float* w_ih = (const float*)d_in[2];
    const float* w_hh = (const float*)d_in[3];
    const float* b_ih = (const float*)d_in[4];
    const float* b_hh = (const float*)d_in[5];
    float* out = (float*)d_out;

    cudaFuncSetAttribute(gru_persistent_kernel,
                         cudaFuncAttributeMaxDynamicSharedMemorySize, SMEM_STEP);

    for (int l = 0; l < 3; l++) {
        dim3 gg(G3 / 128, TB / 128, 2);
        gemm_gi_kernel<<<gg, 256>>>(x, w_ih, b_ih, l);
        init_h_kernel<<<(2 * B_ * H_ / 2 + 255) / 256, 256>>>(h0, l);
        gru_persistent_kernel<<<128, 544, SMEM_STEP>>>(w_hh, b_hh, h0, out, l);
    }
}

// round 12
// speedup vs baseline: 1.5686x; 1.1024x over previous
#include <cuda_runtime.h>
#include <cuda_fp16.h>

#define T_  256
#define B_  64
#define H_  1024
#define G3  3072
#define I_  2048
#define TB  16384   // T_*B_

#define NSLOT      8
// smem words: Ws[48*512] | Hb[8][2048] | red[3072] | mbar[32]
#define WS_WORDS   (48 * 512)                // W: 96KB fp16
#define HB_SLOT_W  2048                      // one 64x64 fp16 chunk (8KB)
#define RED_OFF    (WS_WORDS + NSLOT * HB_SLOT_W)
#define RED_WORDS  3072
#define MBAR_W     (RED_OFF + RED_WORDS)
#define SMEM_STEP  ((MBAR_W + 32) * 4)       // ~173KB (1 CTA/SM)

// ---------------- scratch ----------------------------------------------------
__device__ float g_gi[2][(size_t)TB * G3];
__device__ float g_buf[2][(size_t)TB * I_];
// h: fp16 pairs; per (parity,dir): 16 chunks x 2048 words; chunk = 64 rows x
// 32 words; word(b,kw) = (kw>>5)*2048 + b*32 + ((kw&31) ^ ((b&7)<<2))
__device__ __align__(1024) unsigned g_htf[2][2][B_ * H_ / 2];
__device__ unsigned g_cflag[2][16];          // per-(dir,chunk) producer counts
__device__ unsigned g_done[2];               // per-dir completed-read counter

// ---------------- helpers ---------------------------------------------------
__device__ __forceinline__ unsigned f2h2(float lo, float hi) {
    unsigned u;                              // pack: lower=lo, upper=hi
    asm("cvt.rn.f16x2.f32 %0, %1, %2;" : "=r"(u) : "f"(hi), "f"(lo));
    return u;
}
__device__ __forceinline__ void mmah(float* c, const unsigned* a, const unsigned* b) {
    asm volatile(
        "mma.sync.aligned.m16n8k16.row.col.f32.f16.f16.f32 "
        "{%0,%1,%2,%3}, {%4,%5,%6,%7}, {%8,%9}, {%0,%1,%2,%3};"
        : "+f"(c[0]), "+f"(c[1]), "+f"(c[2]), "+f"(c[3])
        : "r"(a[0]), "r"(a[1]), "r"(a[2]), "r"(a[3]), "r"(b[0]), "r"(b[1]));
}
__device__ __forceinline__ void mbar_wait(unsigned mb, unsigned par) {
    asm volatile(
        "{\n\t.reg .pred P;\nW_%=:\n\t"
        "mbarrier.try_wait.parity.shared::cta.b64 P, [%0], %1;\n\t"
        "@!P bra W_%=;\n\t}" :: "r"(mb), "r"(par) : "memory");
}
__device__ __forceinline__ unsigned ldacq(const unsigned* p) {
    unsigned v;
    asm volatile("ld.acquire.gpu.global.u32 %0, [%1];" : "=r"(v) : "l"(p) : "memory");
    return v;
}
// word index of h pair (b, kw) in g_htf  (kw = k/2, 0..511)
__device__ __forceinline__ int widx(int b, int kw) {
    return (kw >> 5) * 2048 + b * 32 + ((kw & 31) ^ ((b & 7) << 2));
}

// ---------------- input projection GEMM (fp16 m16n8k16) ---------------------
__global__ __launch_bounds__(256) void gemm_gi_kernel(
    const float* __restrict__ x, const float* __restrict__ w_ih,
    const float* __restrict__ b_ih, int l)
{
    const int d = blockIdx.z;
    const float* A    = (l == 0) ? x : g_buf[l - 1];
    const float* W    = w_ih + (size_t)(l * 2 + d) * G3 * I_;
    const float* bias = b_ih + (l * 2 + d) * G3;
    float* C = g_gi[d];

    __shared__ unsigned As[128 * 20];
    __shared__ unsigned Bs[128 * 20];

    const int tid  = threadIdx.x;
    const int lane = tid & 31, warp = tid >> 5;
    const int wm = (warp & 1) * 64, wn = (warp >> 1) * 32;
    const int m0 = blockIdx.y * 128, n0 = blockIdx.x * 128;
    const int g8 = lane >> 2, tg = lane & 3;

    float acc[4][4][4];
    #pragma unroll
    for (int a = 0; a < 4; a++)
        #pragma unroll
        for (int b = 0; b < 4; b++)
            #pragma unroll
            for (int i = 0; i < 4; i++) acc[a][b][i] = 0.f;

    for (int kt = 0; kt < I_; kt += 32) {
        #pragma unroll
        for (int i = 0; i < 4; i++) {            // A tile 128x32 f32 -> h2
            int idx = tid + 256 * i;
            int row = idx >> 3, c4 = (idx & 7) * 4, wc = (idx & 7) * 2;
            float4 v = *reinterpret_cast<const float4*>(
                &A[(size_t)(m0 + row) * I_ + kt + c4]);
            uint2 u = make_uint2(f2h2(v.x, v.y), f2h2(v.z, v.w));
            *reinterpret_cast<uint2*>(&As[row * 20 + wc]) = u;
        }
        #pragma unroll
        for (int i = 0; i < 4; i++) {            // B tile 128x32 (W rows)
            int idx = tid + 256 * i;
            int row = idx >> 3, c4 = (idx & 7) * 4, wc = (idx & 7) * 2;
            float4 v = *reinterpret_cast<const float4*>(
                &W[(size_t)(n0 + row) * I_ + kt + c4]);
            uint2 u = make_uint2(f2h2(v.x, v.y), f2h2(v.z, v.w));
            *reinterpret_cast<uint2*>(&Bs[row * 20 + wc]) = u;
        }
        __syncthreads();
        #pragma unroll
        for (int kk2 = 0; kk2 < 16; kk2 += 8) {  // two k16 mma steps
            unsigned af[4][4], bf[4][2];
            #pragma unroll
            for (int mt = 0; mt < 4; mt++) {
                int r = wm + mt * 16 + g8;
                af[mt][0] = As[r * 20 + kk2 + tg];
                af[mt][1] = As[(r + 8) * 20 + kk2 + tg];
                af[mt][2] = As[r * 20 + kk2 + tg + 4];
                af[mt][3] = As[(r + 8) * 20 + kk2 + tg + 4];
            }
            #pragma unroll
            for (int nt = 0; nt < 4; nt++) {
                int r = wn + nt * 8 + g8;
                bf[nt][0] = Bs[r * 20 + kk2 + tg];
                bf[nt][1] = Bs[r * 20 + kk2 + tg + 4];
            }
            #pragma unroll
            for (int mt = 0; mt < 4; mt++)
                #pragma unroll
                for (int nt = 0; nt < 4; nt++)
                    mmah(acc[mt][nt], af[mt], bf[nt]);
        }
        __syncthreads();
    }
    #pragma unroll
    for (int mt = 0; mt < 4; mt++)
        #pragma unroll
        for (int nt = 0; nt < 4; nt++)
            #pragma unroll
            for (int i = 0; i < 4; i++) {
                int row = m0 + wm + mt * 16 + g8 + 8 * (i >> 1);
                int col = n0 + wn + nt * 8 + 2 * tg + (i & 1);
                C[(size_t)row * G3 + col] = acc[mt][nt][i] + __ldg(&bias[col]);
            }
}

// ---------------- h0 init & flag reset --------------------------------------
__global__ void init_h_kernel(const float* __restrict__ h0, int l)
{
    int i = blockIdx.x * blockDim.x + threadIdx.x;
    if (i < 2 * B_ * H_ / 2) {
        int dir = i >> 15, w = i & 32767;
        int b = w >> 9, kw = w & 511;
        const float* p = &h0[(size_t)(2 * l + dir) * B_ * H_ + (size_t)b * H_ + 2 * kw];
        g_htf[0][dir][widx(b, kw)] = f2h2(p[0], p[1]);
    }
    if (i < 32) g_cflag[i >> 4][i & 15] = 4u;   // h0 counts as step-0 data
    if (i < 2)  g_done[i] = 0u;
}

// ---------------- persistent recurrent kernel (fp16, 8-deep TMA pipe) -------
// 128 CTAs (1/SM), 544 threads: 16 compute warps (ks x jh x rb) + 1 control.
// W_hh slice 48x1024 fp16 (96KB, swizzled) resident all 256 steps. h chunks
// (8KB) streamed via TMA into an 8-slot ring: control warp runs up to 8
// chunks ahead (across step boundaries), amortizing TMA latency 8x.
extern __shared__ unsigned smem_dyn[];

__global__ __launch_bounds__(544, 1) void gru_persistent_kernel(
    const float* __restrict__ w_hh, const float* __restrict__ b_hh,
    const float* __restrict__ h0, float* __restrict__ d_out, int l)
{
    const int cta = blockIdx.x;
    const int dir = cta >> 6;
    const int j0  = (cta & 63) * 16;
    const int cj  = (cta & 63) >> 2;         // chunk this CTA co-produces
    const float* Wg = w_hh + (size_t)(l * 2 + dir) * G3 * H_;
    const float* bh = b_hh + (l * 2 + dir) * G3;
    float* y = (l == 2) ? d_out : g_buf[l];

    unsigned* Ws = smem_dyn;                 // 48*512 words, swizzled
    unsigned* Hb = smem_dyn + WS_WORDS;      // 8 x 2048-word TMA ring
    float* red = reinterpret_cast<float*>(smem_dyn + RED_OFF);
    const unsigned hb_u32 = (unsigned)__cvta_generic_to_shared(Hb);
    const unsigned mb_full  = (unsigned)__cvta_generic_to_shared(smem_dyn + MBAR_W);
    const unsigned mb_empty = mb_full + NSLOT * 8;

    const int tid  = threadIdx.x;
    const int lane = tid & 31, warp = tid >> 5;
    const int ks = (warp < 16) ? (warp >> 3) : 0;    // K half
    const int rb = (warp & 3) * 16;          // B rows of this warp
    const int jh = (warp >> 2) & 1;          // j half (0,1)
    const int gq = lane >> 2, tg = lane & 3;
    const unsigned swz = (unsigned)(gq << 2);
    const int kclo = ks * 16;                // word base within chunk's 32

    // ---- load W once: row=gate*16+jj, word(row,wc)=row*512+(wc^((row&7)<<2))
    if (tid < 512) {
        #pragma unroll 4
        for (int i = 0; i < 24; i++) {
            int idx = tid + 512 * i;         // 12288 float4 granules
            int row = idx >> 8, c4 = (idx & 255) * 4, wc = (idx & 255) * 2;
            int g = row >> 4, jj = row & 15;
            float4 v = *reinterpret_cast<const float4*>(
                &Wg[(size_t)(g * H_ + j0 + jj) * H_ + c4]);
            uint2 u = make_uint2(f2h2(v.x, v.y), f2h2(v.z, v.w));
            *reinterpret_cast<uint2*>(
                &Ws[row * 512 + (wc ^ ((row & 7) << 2))]) = u;
        }
    }

    // ---- bias & initial h_prev registers (ks==0 warps) ----
    const int jA = j0 + jh * 8 + 2 * tg;
    float bhv[3][2], hpv[4];
    if (warp < 16 && ks == 0) {
        #pragma unroll
        for (int g = 0; g < 3; g++) {
            bhv[g][0] = __ldg(&bh[g * H_ + jA]);
            bhv[g][1] = __ldg(&bh[g * H_ + jA + 1]);
        }
        #pragma unroll
        for (int i = 0; i < 4; i++) {
            int b = rb + gq + 8 * (i >> 1);
            hpv[i] = __ldg(&h0[(size_t)(2 * l + dir) * B_ * H_
                               + (size_t)b * H_ + jA + (i & 1)]);
        }
    }

    // ---- mbarriers: full cnt 1 (tx), empty cnt 16 ----
    if (tid == 0) {
        #pragma unroll
        for (int m = 0; m < NSLOT; m++) {
            asm volatile("mbarrier.init.shared.b64 [%0], 1;"
                         :: "r"(mb_full + m * 8) : "memory");
            asm volatile("mbarrier.init.shared.b64 [%0], 16;"
                         :: "r"(mb_empty + m * 8) : "memory");
        }
        asm volatile("fence.proxy.async.shared::cta;" ::: "memory");
    }
    __syncthreads();

    unsigned fuse[NSLOT] = {0}, euse[NSLOT] = {0};

    for (int s = 0; s < T_; s++) {
        const int t = dir ? (T_ - 1 - s) : s;
        const unsigned* src = g_htf[s & 1][dir];
        unsigned* dstg = g_htf[(s + 1) & 1][dir];

        if (warp == 16 && lane == 0) {
            // -------- control: issue all 16 chunk TMAs (8-deep ring) ------
            const unsigned tgt = 4u * (unsigned)(s + 1);
            for (int c = 0; c < 16; c++) {
                int slot = c & (NSLOT - 1);
                if (euse[slot] > 0)
                    mbar_wait(mb_empty + slot * 8, (euse[slot] - 1) & 1);
                euse[slot]++;
                while (ldacq(&g_cflag[dir][c]) < tgt) __nanosleep(20);
                unsigned fm = mb_full + slot * 8;
                asm volatile("mbarrier.arrive.expect_tx.shared.b64 _, [%0], %1;"
                             :: "r"(fm), "r"(8192u) : "memory");
                asm volatile(
                    "cp.async.bulk.shared::cta.global.mbarrier::complete_tx::bytes "
                    "[%0], [%1], %2, [%3];"
                    :: "r"(hb_u32 + slot * (HB_SLOT_W * 4)),
                       "l"(src + c * HB_SLOT_W), "r"(8192u), "r"(fm) : "memory");
            }
        }

        float acc[3][4];
        #pragma unroll
        for (int g = 0; g < 3; g++)
            #pragma unroll
            for (int i = 0; i < 4; i++) acc[g][i] = 0.f;

        float giv[3][4];
        if (warp < 16 && ks == 0) {          // gi prefetch overlaps GEMM
            #pragma unroll
            for (int i = 0; i < 4; i++) {
                int b = rb + gq + 8 * (i >> 1);
                int j = jA + (i & 1);
                const float* gi = g_gi[dir] + (size_t)(t * B_ + b) * G3;
                giv[0][i] = __ldg(&gi[j]);
                giv[1][i] = __ldg(&gi[H_ + j]);
                giv[2][i] = __ldg(&gi[2 * H_ + j]);
            }
        }

        if (warp < 16) {
            // -------- compute warps: consume 16 chunks --------------------
            for (int c = 0; c < 16; c++) {
                int slot = c & (NSLOT - 1);
                mbar_wait(mb_full + slot * 8, fuse[slot] & 1);
                fuse[slot]++;

                const unsigned* hb = Hb + slot * HB_SLOT_W;
                #pragma unroll
                for (int kk2 = 0; kk2 < 16; kk2 += 8) {
                    const int kc = kclo + kk2;           // word col in chunk
                    unsigned af[4];
                    int r0 = rb + gq;
                    af[0] = hb[r0 * 32       + ((unsigned)(kc + tg)     ^ swz)];
                    af[1] = hb[(r0 + 8) * 32 + ((unsigned)(kc + tg)     ^ swz)];
                    af[2] = hb[r0 * 32       + ((unsigned)(kc + tg + 4) ^ swz)];
                    af[3] = hb[(r0 + 8) * 32 + ((unsigned)(kc + tg + 4) ^ swz)];
                    const int kw = c * 32 + kc;          // global word in W
                    #pragma unroll
                    for (int g = 0; g < 3; g++) {
                        const int wr = g * 16 + jh * 8 + gq;
                        unsigned bf[2];
                        bf[0] = Ws[wr * 512 + ((unsigned)(kw + tg) ^ swz)];
                        bf[1] = Ws[wr * 512 + ((unsigned)(kw + tg + 4) ^ swz)];
                        mmah(acc[g], af, bf);
                    }
                }
                if (lane == 0)
                    asm volatile("mbarrier.arrive.shared.b64 _, [%0];"
                                 :: "r"(mb_empty + slot * 8) : "memory");
            }
        }

        __syncthreads();                     // sync1: all chunks consumed

        // ---- K-split partials into dedicated red region ----
        if (warp < 16 && ks == 1) {
            int base = ((warp & 7) * 32 + lane) * 12;
            #pragma unroll
            for (int g = 0; g < 3; g++)
                #pragma unroll
                for (int i = 0; i < 4; i++) red[base + g * 4 + i] = acc[g][i];
        }
        if (tid == 0 && s > 0) {             // lagged h-buffer write gate
            const unsigned tgt = 64u * (unsigned)s;
            while (ldacq(&g_done[dir]) < tgt) __nanosleep(20);
        }
        __syncthreads();                     // sync2

        if (warp < 16 && ks == 0) {
            int base = (warp * 32 + lane) * 12;
            #pragma unroll
            for (int g = 0; g < 3; g++)
                #pragma unroll
                for (int i = 0; i < 4; i++) acc[g][i] += red[base + g * 4 + i];

            #pragma unroll
            for (int i = 0; i < 4; i++) {
                float r = 1.f / (1.f + expf(-(giv[0][i] + acc[0][i] + bhv[0][i & 1])));
                float z = 1.f / (1.f + expf(-(giv[1][i] + acc[1][i] + bhv[1][i & 1])));
                float n = tanhf(giv[2][i] + r * (acc[2][i] + bhv[2][i & 1]));
                hpv[i] = (1.f - z) * n + z * hpv[i];
            }
            // h store: one half2 word per b (pairs i=0,1 and i=2,3)
            const int kw = jA >> 1;
            #pragma unroll
            for (int p = 0; p < 2; p++) {
                int b = rb + gq + 8 * p;
                __stcg(&dstg[widx(b, kw)], f2h2(hpv[2 * p], hpv[2 * p + 1]));
            }
        }
        __syncthreads();                     // sync3: h stores done CTA-wide

        if (tid == 0) {
            __threadfence();                 // cumulative release of h stores
            atomicAdd(&g_cflag[dir][cj], 1u);
            atomicAdd(&g_done[dir], 1u);
        }
        if (warp < 16 && ks == 0) {          // y stores off the critical path
            #pragma unroll
            for (int p = 0; p < 2; p++) {
                int b = rb + gq + 8 * p;
                float2 v = make_float2(hpv[2 * p], hpv[2 * p + 1]);
                *reinterpret_cast<float2*>(
                    &y[(size_t)(t * B_ + b) * 2048 + dir * H_ + jA]) = v;
            }
        }
    }
}

// ---------------- launch ------------------------------------------------------
extern "C" void kernel_launch(void* const* d_in, const int* in_sizes, int n_in,
                              void* d_out, int out_size)
{
    const float* x    = (const float*)d_in[0];
    const float* h0   = (const float*)d_in[1];
    const float* w_ih = (const float*)d_in[2];
    const float* w_hh = (const float*)d_in[3];
    const float* b_ih = (const float*)d_in[4];
    const float* b_hh = (const float*)d_in[5];
    float* out = (float*)d_out;

    cudaFuncSetAttribute(gru_persistent_kernel,
                         cudaFuncAttributeMaxDynamicSharedMemorySize, SMEM_STEP);

    for (int l = 0; l < 3; l++) {
        dim3 gg(G3 / 128, TB / 128, 2);
        gemm_gi_kernel<<<gg, 256>>>(x, w_ih, b_ih, l);
        init_h_kernel<<<(2 * B_ * H_ / 2 + 255) / 256, 256>>>(h0, l);
        gru_persistent_kernel<<<128, 544, SMEM_STEP>>>(w_hh, b_hh, h0, out, l);
    }
}